// round 1
// baseline (speedup 1.0000x reference)
#include <cuda_runtime.h>
#include <cstdint>
#include <cstddef>

// Problem constants
#define E_DIM   256
#define FF_DIM  1024
#define H_HEADS 8
#define D_HEAD  32
#define NH      8
#define B_SZ    2
#define N_SEQ   8192
#define M_ROWS  (B_SZ * N_SEQ * NH)      // 131072
#define BN_TOK  (B_SZ * N_SEQ)           // 16384

// Scratch (device globals: allocation-free rule)
__device__ float g_t   [(size_t)M_ROWS * E_DIM];
__device__ float g_q   [(size_t)M_ROWS * E_DIM];
__device__ float g_k   [(size_t)M_ROWS * E_DIM];
__device__ float g_v   [(size_t)M_ROWS * E_DIM];
__device__ float g_attn[(size_t)M_ROWS * E_DIM];
__device__ float g_ff  [(size_t)M_ROWS * FF_DIM];

// ---------------------------------------------------------------------------
// Generic tiled SGEMM: C[M,N] = A[M,K] @ W[K,N] (+bias) (+silu)
// BM=128, BN=64, BK=16, 256 threads, 8x4 register tile per thread.
// ---------------------------------------------------------------------------
#define BM 128
#define BN 64
#define BK 16
#define TM 8
#define TN 4

__global__ __launch_bounds__(256)
void gemm_kernel(const float* __restrict__ A, const float* __restrict__ Bw,
                 const float* __restrict__ bias, float* __restrict__ C,
                 int M, int K, int N, int act)
{
    __shared__ float As[BK][BM];
    __shared__ float Bs[BK][BN];

    const int tid = threadIdx.x;
    const int block_m = blockIdx.y * BM;
    const int block_n = blockIdx.x * BN;
    const int tx = tid & 15;   // col group (16)
    const int ty = tid >> 4;   // row group (16)

    float acc[TM][TN];
#pragma unroll
    for (int i = 0; i < TM; i++)
#pragma unroll
        for (int j = 0; j < TN; j++) acc[i][j] = 0.f;

    for (int k0 = 0; k0 < K; k0 += BK) {
        // Load A tile 128x16 -> As[k][m] (transposed). 512 float4, 2 per thread.
#pragma unroll
        for (int i = 0; i < 2; i++) {
            int l  = tid * 2 + i;
            int r  = l >> 2;
            int cv = (l & 3) * 4;
            float4 vv = *(const float4*)&A[(size_t)(block_m + r) * K + k0 + cv];
            As[cv + 0][r] = vv.x;
            As[cv + 1][r] = vv.y;
            As[cv + 2][r] = vv.z;
            As[cv + 3][r] = vv.w;
        }
        // Load B tile 16x64 -> Bs. 256 float4, 1 per thread.
        {
            int r  = tid >> 4;
            int cv = (tid & 15) * 4;
            float4 vv = *(const float4*)&Bw[(size_t)(k0 + r) * N + block_n + cv];
            *(float4*)&Bs[r][cv] = vv;
        }
        __syncthreads();

#pragma unroll
        for (int kk = 0; kk < BK; kk++) {
            float a[TM], b[TN];
#pragma unroll
            for (int i = 0; i < TM; i++) a[i] = As[kk][ty * TM + i];
#pragma unroll
            for (int j = 0; j < TN; j++) b[j] = Bs[kk][tx * TN + j];
#pragma unroll
            for (int i = 0; i < TM; i++)
#pragma unroll
                for (int j = 0; j < TN; j++) acc[i][j] += a[i] * b[j];
        }
        __syncthreads();
    }

    // Epilogue: bias + optional silu, vectorized store
#pragma unroll
    for (int i = 0; i < TM; i++) {
        int m = block_m + ty * TM + i;
        int n = block_n + tx * TN;
        float4 o;
        float vv[TN];
#pragma unroll
        for (int j = 0; j < TN; j++) {
            float val = acc[i][j];
            if (bias) val += bias[n + j];
            if (act == 1) val = val / (1.f + expf(-val));  // silu
            vv[j] = val;
        }
        o.x = vv[0]; o.y = vv[1]; o.z = vv[2]; o.w = vv[3];
        *(float4*)&C[(size_t)m * N + n] = o;
    }
}

// ---------------------------------------------------------------------------
// LayerNorm: out[row] = LN(a[row] (+ res[row])) * g + b   (E=256, warp/row)
// ---------------------------------------------------------------------------
__global__ __launch_bounds__(256)
void ln_kernel(const float* __restrict__ a, const float* __restrict__ res,
               const float* __restrict__ g, const float* __restrict__ b,
               float* __restrict__ out)
{
    int row  = blockIdx.x * 8 + (threadIdx.x >> 5);
    int lane = threadIdx.x & 31;
    size_t base = (size_t)row * E_DIM;

    float vals[8];
    float s = 0.f, s2 = 0.f;
#pragma unroll
    for (int i = 0; i < 8; i++) {
        float x = a[base + lane + i * 32];
        if (res) x += res[base + lane + i * 32];
        vals[i] = x;
        s += x; s2 += x * x;
    }
#pragma unroll
    for (int o = 16; o; o >>= 1) {
        s  += __shfl_xor_sync(0xffffffffu, s,  o);
        s2 += __shfl_xor_sync(0xffffffffu, s2, o);
    }
    float m   = s  * (1.f / E_DIM);
    float var = s2 * (1.f / E_DIM) - m * m;
    float inv = rsqrtf(var + 1e-5f);
#pragma unroll
    for (int i = 0; i < 8; i++) {
        int c = lane + i * 32;
        out[base + c] = (vals[i] - m) * inv * g[c] + b[c];
    }
}

// ---------------------------------------------------------------------------
// Attention: per-token (bn) attention over NH=8 positions, H=8 heads, d=32.
// Includes positional-bias MLP: bias[ki][h] = silu([p1,p2]@W_pos) @ W_bias.
// One CTA (256 threads) per bn token.
// ---------------------------------------------------------------------------
__global__ __launch_bounds__(256)
void attn_kernel(const float* __restrict__ q, const float* __restrict__ k,
                 const float* __restrict__ v,
                 const float* __restrict__ pos1, const float* __restrict__ pos2,
                 const float* __restrict__ W_pos, const float* __restrict__ W_bias,
                 float* __restrict__ out)
{
    int bn  = blockIdx.x;
    int tid = threadIdx.x;
    size_t base = (size_t)bn * NH * E_DIM;

    __shared__ float sq[NH][E_DIM];
    __shared__ float sk[NH][E_DIM];
    __shared__ float sv[NH][E_DIM];
    __shared__ float sbias[NH][H_HEADS];       // [key nh][head]
    __shared__ float satt[H_HEADS][NH][NH];    // [h][q][k]

    // Load q,k,v tiles: 8x256 floats each = 512 float4, 2 per thread each.
#pragma unroll
    for (int i = 0; i < 2; i++) {
        int l  = tid + i * 256;
        int r  = l >> 6;
        int cv = (l & 63) * 4;
        *(float4*)&sq[r][cv] = *(const float4*)&q[base + (size_t)r * E_DIM + cv];
        *(float4*)&sk[r][cv] = *(const float4*)&k[base + (size_t)r * E_DIM + cv];
        *(float4*)&sv[r][cv] = *(const float4*)&v[base + (size_t)r * E_DIM + cv];
    }

    // Positional bias: 64 (nh,h) pairs
    if (tid < NH * H_HEADS) {
        int nh = tid >> 3;
        int h  = tid & 7;
        size_t pbase = ((size_t)bn * NH + nh) * 2;
        float p0 = pos1[pbase + 0], p1 = pos1[pbase + 1];
        float p2 = pos2[pbase + 0], p3 = pos2[pbase + 1];
        float acc = 0.f;
#pragma unroll
        for (int pe = 0; pe < 32; pe++) {
            float e = p0 * W_pos[0 * 32 + pe] + p1 * W_pos[1 * 32 + pe]
                    + p2 * W_pos[2 * 32 + pe] + p3 * W_pos[3 * 32 + pe];
            e = e / (1.f + expf(-e));          // silu
            acc += e * W_bias[pe * H_HEADS + h];
        }
        sbias[nh][h] = acc;
    }
    __syncthreads();

    // Scores: 512 (h,qi,ki) triples, 2 per thread
    const float scale = 0.17677669529663687f;  // 1/sqrt(32)
#pragma unroll
    for (int it = 0; it < 2; it++) {
        int idx = tid + it * 256;
        int h  = idx >> 6;
        int qi = (idx >> 3) & 7;
        int ki = idx & 7;
        float s = 0.f;
        const float* qp = &sq[qi][h * D_HEAD];
        const float* kp = &sk[ki][h * D_HEAD];
#pragma unroll
        for (int d = 0; d < D_HEAD; d++) s += qp[d] * kp[d];
        satt[h][qi][ki] = s * scale + sbias[ki][h];
    }
    __syncthreads();

    // Softmax over ki: 64 rows
    if (tid < H_HEADS * NH) {
        int h  = tid >> 3;
        int qi = tid & 7;
        float mx = satt[h][qi][0];
#pragma unroll
        for (int ki = 1; ki < NH; ki++) mx = fmaxf(mx, satt[h][qi][ki]);
        float sum = 0.f;
        float ex[NH];
#pragma unroll
        for (int ki = 0; ki < NH; ki++) { ex[ki] = expf(satt[h][qi][ki] - mx); sum += ex[ki]; }
        float rs = 1.f / sum;
#pragma unroll
        for (int ki = 0; ki < NH; ki++) satt[h][qi][ki] = ex[ki] * rs;
    }
    __syncthreads();

    // Output: out[qi][h*32+d] = sum_ki att[h][qi][ki] * v[ki][h*32+d]
#pragma unroll
    for (int it = 0; it < 8; it++) {
        int idx = tid + it * 256;
        int qi = idx >> 8;
        int c  = idx & 255;
        int h  = c >> 5;
        float o = 0.f;
#pragma unroll
        for (int ki = 0; ki < NH; ki++) o += satt[h][qi][ki] * sv[ki][c];
        out[base + (size_t)qi * E_DIM + c] = o;
    }
}

// ---------------------------------------------------------------------------
// Host launcher
// ---------------------------------------------------------------------------
extern "C" void kernel_launch(void* const* d_in, const int* in_sizes, int n_in,
                              void* d_out, int out_size)
{
    const float* x     = (const float*)d_in[0];
    const float* pos1  = (const float*)d_in[1];
    const float* pos2  = (const float*)d_in[2];
    const float* W_in  = (const float*)d_in[3];
    const float* gin   = (const float*)d_in[4];
    const float* bin   = (const float*)d_in[5];
    const float* Wq    = (const float*)d_in[6];
    const float* bq    = (const float*)d_in[7];
    const float* Wk    = (const float*)d_in[8];
    const float* bk    = (const float*)d_in[9];
    const float* Wv    = (const float*)d_in[10];
    const float* bv    = (const float*)d_in[11];
    const float* Wo    = (const float*)d_in[12];
    const float* bo    = (const float*)d_in[13];
    const float* W_pos = (const float*)d_in[14];
    const float* W_bias= (const float*)d_in[15];
    const float* W_ff1 = (const float*)d_in[16];
    const float* W_ff2 = (const float*)d_in[17];
    const float* g1    = (const float*)d_in[18];
    const float* b1    = (const float*)d_in[19];
    const float* g2    = (const float*)d_in[20];
    const float* b2    = (const float*)d_in[21];

    float *t, *qb, *kb, *vb, *attn, *ff;
    cudaGetSymbolAddress((void**)&t,    g_t);
    cudaGetSymbolAddress((void**)&qb,   g_q);
    cudaGetSymbolAddress((void**)&kb,   g_k);
    cudaGetSymbolAddress((void**)&vb,   g_v);
    cudaGetSymbolAddress((void**)&attn, g_attn);
    cudaGetSymbolAddress((void**)&ff,   g_ff);

    dim3 blk(256);
    dim3 g256(E_DIM / BN,  M_ROWS / BM);   // (4, 1024)
    dim3 g1024(FF_DIM / BN, M_ROWS / BM);  // (16, 1024)

    // 1. t = LN(x @ W_in)
    gemm_kernel<<<g256, blk>>>(x, W_in, nullptr, t, M_ROWS, E_DIM, E_DIM, 0);
    ln_kernel<<<BN_TOK, 256>>>(t, nullptr, gin, bin, t);

    // 2. q, k, v projections
    gemm_kernel<<<g256, blk>>>(t, Wq, bq, qb, M_ROWS, E_DIM, E_DIM, 0);
    gemm_kernel<<<g256, blk>>>(t, Wk, bk, kb, M_ROWS, E_DIM, E_DIM, 0);
    gemm_kernel<<<g256, blk>>>(t, Wv, bv, vb, M_ROWS, E_DIM, E_DIM, 0);

    // 3. attention (+positional bias) over NH=8 per token
    attn_kernel<<<BN_TOK, 256>>>(qb, kb, vb, pos1, pos2, W_pos, W_bias, attn);

    // 4. o = attn @ Wo + bo   (into qb, free now)
    gemm_kernel<<<g256, blk>>>(attn, Wo, bo, qb, M_ROWS, E_DIM, E_DIM, 0);

    // 5. h1 = LN(t + o)  -> kb
    ln_kernel<<<BN_TOK, 256>>>(qb, t, g1, b1, kb);

    // 6. ff = silu(h1 @ W_ff1)
    gemm_kernel<<<g1024, blk>>>(kb, W_ff1, nullptr, ff, M_ROWS, E_DIM, FF_DIM, 1);

    // 7. o2 = ff @ W_ff2  (into vb)
    gemm_kernel<<<g256, blk>>>(ff, W_ff2, nullptr, vb, M_ROWS, FF_DIM, E_DIM, 0);

    // 8. out = LN(h1 + o2)
    ln_kernel<<<BN_TOK, 256>>>(vb, kb, g2, b2, (float*)d_out);
}

// round 2
// speedup vs baseline: 2.7095x; 2.7095x over previous
#include <cuda_runtime.h>
#include <cstdint>
#include <cstddef>

// Problem constants
#define E_DIM   256
#define FF_DIM  1024
#define H_HEADS 8
#define D_HEAD  32
#define NH      8
#define B_SZ    2
#define N_SEQ   8192
#define M_ROWS  (B_SZ * N_SEQ * NH)      // 131072
#define BN_TOK  (B_SZ * N_SEQ)           // 16384

// Scratch (device globals: allocation-free rule)
__device__ float g_t   [(size_t)M_ROWS * E_DIM];
__device__ float g_q   [(size_t)M_ROWS * E_DIM];
__device__ float g_k   [(size_t)M_ROWS * E_DIM];
__device__ float g_v   [(size_t)M_ROWS * E_DIM];
__device__ float g_attn[(size_t)M_ROWS * E_DIM];
__device__ float g_ff  [(size_t)M_ROWS * FF_DIM];

// Transposed weights [N][K]
__device__ float g_wt_in[E_DIM * E_DIM];
__device__ float g_wt_q [E_DIM * E_DIM];
__device__ float g_wt_k [E_DIM * E_DIM];
__device__ float g_wt_v [E_DIM * E_DIM];
__device__ float g_wt_o [E_DIM * E_DIM];
__device__ float g_wt_f1[E_DIM * FF_DIM];   // [1024][256]
__device__ float g_wt_f2[FF_DIM * E_DIM];   // [256][1024]

__device__ __forceinline__ uint32_t f2tf(float x) {
    uint32_t u;
    asm("cvt.rna.tf32.f32 %0, %1;" : "=r"(u) : "f"(x));
    return u;
}
__device__ __forceinline__ uint32_t smem_u32(const void* p) {
    return (uint32_t)__cvta_generic_to_shared(p);
}

// ---------------------------------------------------------------------------
// Weight transpose: Wt[n][k] = W[k][n]
// ---------------------------------------------------------------------------
__global__ __launch_bounds__(256)
void transpose_kernel(const float* __restrict__ W, float* __restrict__ Wt, int K, int N)
{
    int idx = blockIdx.x * 256 + threadIdx.x;
    if (idx >= K * N) return;
    int k = idx / N, n = idx - k * N;
    Wt[(size_t)n * K + k] = W[idx];
}

// ---------------------------------------------------------------------------
// TF32 tensor-core GEMM: C[M,N] = A[M,K] @ Wt[N,K]^T (+bias) (+silu)
// CTA tile 128x128x32, 8 warps, warp tile 64x32, mma.m16n8k8.tf32
// ---------------------------------------------------------------------------
#define BK 32

__global__ __launch_bounds__(256)
void gemm_tc(const float* __restrict__ A, const float* __restrict__ Wt,
             const float* __restrict__ bias, float* __restrict__ C,
             int M, int K, int N, int act)
{
    __shared__ uint32_t As[128][36];   // [m][k], pitch 144B
    __shared__ uint32_t Bs[128][36];   // [n][k]

    const int tid  = threadIdx.x;
    const int lane = tid & 31;
    const int warp = tid >> 5;
    const int wm   = (warp & 1) * 64;       // warp row offset in tile
    const int wn   = (warp >> 1) * 32;      // warp col offset in tile
    const int g    = lane >> 2;
    const int tig  = lane & 3;
    const int r8   = lane & 7;
    const int sel  = lane >> 3;

    const size_t block_m = (size_t)blockIdx.y * 128;
    const size_t block_n = (size_t)blockIdx.x * 128;

    float acc[4][4][4];
#pragma unroll
    for (int mt = 0; mt < 4; mt++)
#pragma unroll
        for (int nt = 0; nt < 4; nt++)
#pragma unroll
            for (int i = 0; i < 4; i++) acc[mt][nt][i] = 0.f;

    // precomputed load indices (4 float4 per thread per operand)
    float4 ra[4], rb[4];
#pragma unroll
    for (int i = 0; i < 4; i++) {
        int idx = i * 256 + tid;
        int row = idx >> 3;
        int kv  = (idx & 7) << 2;
        ra[i] = *(const float4*)&A [(block_m + row) * K + kv];
        rb[i] = *(const float4*)&Wt[(block_n + row) * K + kv];
    }

    for (int k0 = 0; k0 < K; k0 += BK) {
        __syncthreads();   // previous iter's mma reads done
#pragma unroll
        for (int i = 0; i < 4; i++) {
            int idx = i * 256 + tid;
            int row = idx >> 3;
            int kv  = (idx & 7) << 2;
            uint4 sa = { f2tf(ra[i].x), f2tf(ra[i].y), f2tf(ra[i].z), f2tf(ra[i].w) };
            *(uint4*)&As[row][kv] = sa;
            uint4 sb = { f2tf(rb[i].x), f2tf(rb[i].y), f2tf(rb[i].z), f2tf(rb[i].w) };
            *(uint4*)&Bs[row][kv] = sb;
        }
        __syncthreads();

        // prefetch next K tile while mma runs
        if (k0 + BK < K) {
#pragma unroll
            for (int i = 0; i < 4; i++) {
                int idx = i * 256 + tid;
                int row = idx >> 3;
                int kv  = (idx & 7) << 2;
                ra[i] = *(const float4*)&A [(block_m + row) * K + k0 + BK + kv];
                rb[i] = *(const float4*)&Wt[(block_n + row) * K + k0 + BK + kv];
            }
        }

#pragma unroll
        for (int kk = 0; kk < 4; kk++) {
            const int kb = kk * 8;

            uint32_t af[4][4];
#pragma unroll
            for (int mt = 0; mt < 4; mt++) {
                int row = wm + mt * 16 + ((sel & 1) ? 8 : 0) + r8;
                int col = kb + ((sel & 2) ? 4 : 0);
                uint32_t addr = smem_u32(&As[row][col]);
                asm volatile(
                    "ldmatrix.sync.aligned.m8n8.x4.shared.b16 {%0,%1,%2,%3}, [%4];"
                    : "=r"(af[mt][0]), "=r"(af[mt][1]), "=r"(af[mt][2]), "=r"(af[mt][3])
                    : "r"(addr));
            }

            uint32_t bf[4][2];
#pragma unroll
            for (int p = 0; p < 2; p++) {
                int row = wn + p * 16 + ((sel & 2) ? 8 : 0) + r8;
                int col = kb + ((sel & 1) ? 4 : 0);
                uint32_t addr = smem_u32(&Bs[row][col]);
                uint32_t t0, t1, t2, t3;
                asm volatile(
                    "ldmatrix.sync.aligned.m8n8.x4.shared.b16 {%0,%1,%2,%3}, [%4];"
                    : "=r"(t0), "=r"(t1), "=r"(t2), "=r"(t3)
                    : "r"(addr));
                bf[2 * p + 0][0] = t0; bf[2 * p + 0][1] = t1;
                bf[2 * p + 1][0] = t2; bf[2 * p + 1][1] = t3;
            }

#pragma unroll
            for (int mt = 0; mt < 4; mt++)
#pragma unroll
                for (int nt = 0; nt < 4; nt++) {
                    asm volatile(
                        "mma.sync.aligned.m16n8k8.row.col.f32.tf32.tf32.f32 "
                        "{%0,%1,%2,%3}, {%4,%5,%6,%7}, {%8,%9}, {%0,%1,%2,%3};"
                        : "+f"(acc[mt][nt][0]), "+f"(acc[mt][nt][1]),
                          "+f"(acc[mt][nt][2]), "+f"(acc[mt][nt][3])
                        : "r"(af[mt][0]), "r"(af[mt][1]), "r"(af[mt][2]), "r"(af[mt][3]),
                          "r"(bf[nt][0]), "r"(bf[nt][1]));
                }
        }
    }

    // Epilogue
#pragma unroll
    for (int mt = 0; mt < 4; mt++) {
#pragma unroll
        for (int nt = 0; nt < 4; nt++) {
            size_t row0 = block_m + wm + mt * 16 + g;
            size_t col  = block_n + wn + nt * 8 + tig * 2;
            float v0 = acc[mt][nt][0], v1 = acc[mt][nt][1];
            float v2 = acc[mt][nt][2], v3 = acc[mt][nt][3];
            if (bias) {
                float b0 = bias[col], b1 = bias[col + 1];
                v0 += b0; v1 += b1; v2 += b0; v3 += b1;
            }
            if (act == 1) {
                v0 = v0 / (1.f + expf(-v0));
                v1 = v1 / (1.f + expf(-v1));
                v2 = v2 / (1.f + expf(-v2));
                v3 = v3 / (1.f + expf(-v3));
            }
            float2 o01 = { v0, v1 };
            float2 o23 = { v2, v3 };
            *(float2*)&C[row0 * N + col]       = o01;
            *(float2*)&C[(row0 + 8) * N + col] = o23;
        }
    }
}

// ---------------------------------------------------------------------------
// LayerNorm: out[row] = LN(a[row] (+ res[row])) * g + b   (E=256, warp/row)
// ---------------------------------------------------------------------------
__global__ __launch_bounds__(256)
void ln_kernel(const float* __restrict__ a, const float* __restrict__ res,
               const float* __restrict__ g, const float* __restrict__ b,
               float* __restrict__ out)
{
    int row  = blockIdx.x * 8 + (threadIdx.x >> 5);
    int lane = threadIdx.x & 31;
    size_t base = (size_t)row * E_DIM;

    float vals[8];
    float s = 0.f, s2 = 0.f;
#pragma unroll
    for (int i = 0; i < 8; i++) {
        float x = a[base + lane + i * 32];
        if (res) x += res[base + lane + i * 32];
        vals[i] = x;
        s += x; s2 += x * x;
    }
#pragma unroll
    for (int o = 16; o; o >>= 1) {
        s  += __shfl_xor_sync(0xffffffffu, s,  o);
        s2 += __shfl_xor_sync(0xffffffffu, s2, o);
    }
    float m   = s  * (1.f / E_DIM);
    float var = s2 * (1.f / E_DIM) - m * m;
    float inv = rsqrtf(var + 1e-5f);
#pragma unroll
    for (int i = 0; i < 8; i++) {
        int c = lane + i * 32;
        out[base + c] = (vals[i] - m) * inv * g[c] + b[c];
    }
}

// ---------------------------------------------------------------------------
// Attention: per-token (bn) attention over NH=8 positions, H=8 heads, d=32.
// ---------------------------------------------------------------------------
__global__ __launch_bounds__(256)
void attn_kernel(const float* __restrict__ q, const float* __restrict__ k,
                 const float* __restrict__ v,
                 const float* __restrict__ pos1, const float* __restrict__ pos2,
                 const float* __restrict__ W_pos, const float* __restrict__ W_bias,
                 float* __restrict__ out)
{
    int bn  = blockIdx.x;
    int tid = threadIdx.x;
    size_t base = (size_t)bn * NH * E_DIM;

    __shared__ float sq[NH][E_DIM];
    __shared__ float sk[NH][E_DIM];
    __shared__ float sv[NH][E_DIM];
    __shared__ float sbias[NH][H_HEADS];       // [key nh][head]
    __shared__ float satt[H_HEADS][NH][NH];    // [h][q][k]

#pragma unroll
    for (int i = 0; i < 2; i++) {
        int l  = tid + i * 256;
        int r  = l >> 6;
        int cv = (l & 63) * 4;
        *(float4*)&sq[r][cv] = *(const float4*)&q[base + (size_t)r * E_DIM + cv];
        *(float4*)&sk[r][cv] = *(const float4*)&k[base + (size_t)r * E_DIM + cv];
        *(float4*)&sv[r][cv] = *(const float4*)&v[base + (size_t)r * E_DIM + cv];
    }

    if (tid < NH * H_HEADS) {
        int nh = tid >> 3;
        int h  = tid & 7;
        size_t pbase = ((size_t)bn * NH + nh) * 2;
        float p0 = pos1[pbase + 0], p1 = pos1[pbase + 1];
        float p2 = pos2[pbase + 0], p3 = pos2[pbase + 1];
        float acc = 0.f;
#pragma unroll
        for (int pe = 0; pe < 32; pe++) {
            float e = p0 * W_pos[0 * 32 + pe] + p1 * W_pos[1 * 32 + pe]
                    + p2 * W_pos[2 * 32 + pe] + p3 * W_pos[3 * 32 + pe];
            e = e / (1.f + expf(-e));
            acc += e * W_bias[pe * H_HEADS + h];
        }
        sbias[nh][h] = acc;
    }
    __syncthreads();

    const float scale = 0.17677669529663687f;  // 1/sqrt(32)
#pragma unroll
    for (int it = 0; it < 2; it++) {
        int idx = tid + it * 256;
        int h  = idx >> 6;
        int qi = (idx >> 3) & 7;
        int ki = idx & 7;
        float s = 0.f;
        const float* qp = &sq[qi][h * D_HEAD];
        const float* kp = &sk[ki][h * D_HEAD];
#pragma unroll
        for (int d = 0; d < D_HEAD; d++) s += qp[d] * kp[d];
        satt[h][qi][ki] = s * scale + sbias[ki][h];
    }
    __syncthreads();

    if (tid < H_HEADS * NH) {
        int h  = tid >> 3;
        int qi = tid & 7;
        float mx = satt[h][qi][0];
#pragma unroll
        for (int ki = 1; ki < NH; ki++) mx = fmaxf(mx, satt[h][qi][ki]);
        float sum = 0.f;
        float ex[NH];
#pragma unroll
        for (int ki = 0; ki < NH; ki++) { ex[ki] = expf(satt[h][qi][ki] - mx); sum += ex[ki]; }
        float rs = 1.f / sum;
#pragma unroll
        for (int ki = 0; ki < NH; ki++) satt[h][qi][ki] = ex[ki] * rs;
    }
    __syncthreads();

#pragma unroll
    for (int it = 0; it < 8; it++) {
        int idx = tid + it * 256;
        int qi = idx >> 8;
        int c  = idx & 255;
        int h  = c >> 5;
        float o = 0.f;
#pragma unroll
        for (int ki = 0; ki < NH; ki++) o += satt[h][qi][ki] * sv[ki][c];
        out[base + (size_t)qi * E_DIM + c] = o;
    }
}

// ---------------------------------------------------------------------------
// Host launcher
// ---------------------------------------------------------------------------
extern "C" void kernel_launch(void* const* d_in, const int* in_sizes, int n_in,
                              void* d_out, int out_size)
{
    const float* x     = (const float*)d_in[0];
    const float* pos1  = (const float*)d_in[1];
    const float* pos2  = (const float*)d_in[2];
    const float* W_in  = (const float*)d_in[3];
    const float* gin   = (const float*)d_in[4];
    const float* bin   = (const float*)d_in[5];
    const float* Wq    = (const float*)d_in[6];
    const float* bq    = (const float*)d_in[7];
    const float* Wk    = (const float*)d_in[8];
    const float* bk    = (const float*)d_in[9];
    const float* Wv    = (const float*)d_in[10];
    const float* bv    = (const float*)d_in[11];
    const float* Wo    = (const float*)d_in[12];
    const float* bo    = (const float*)d_in[13];
    const float* W_pos = (const float*)d_in[14];
    const float* W_bias= (const float*)d_in[15];
    const float* W_ff1 = (const float*)d_in[16];
    const float* W_ff2 = (const float*)d_in[17];
    const float* g1    = (const float*)d_in[18];
    const float* b1    = (const float*)d_in[19];
    const float* g2    = (const float*)d_in[20];
    const float* b2    = (const float*)d_in[21];

    float *t, *qb, *kb, *vb, *attn, *ff;
    float *wt_in, *wt_q, *wt_k, *wt_v, *wt_o, *wt_f1, *wt_f2;
    cudaGetSymbolAddress((void**)&t,     g_t);
    cudaGetSymbolAddress((void**)&qb,    g_q);
    cudaGetSymbolAddress((void**)&kb,    g_k);
    cudaGetSymbolAddress((void**)&vb,    g_v);
    cudaGetSymbolAddress((void**)&attn,  g_attn);
    cudaGetSymbolAddress((void**)&ff,    g_ff);
    cudaGetSymbolAddress((void**)&wt_in, g_wt_in);
    cudaGetSymbolAddress((void**)&wt_q,  g_wt_q);
    cudaGetSymbolAddress((void**)&wt_k,  g_wt_k);
    cudaGetSymbolAddress((void**)&wt_v,  g_wt_v);
    cudaGetSymbolAddress((void**)&wt_o,  g_wt_o);
    cudaGetSymbolAddress((void**)&wt_f1, g_wt_f1);
    cudaGetSymbolAddress((void**)&wt_f2, g_wt_f2);

    // Transpose all weights to [N][K]
    int nEE = E_DIM * E_DIM, nEF = E_DIM * FF_DIM;
    transpose_kernel<<<(nEE + 255) / 256, 256>>>(W_in,  wt_in, E_DIM, E_DIM);
    transpose_kernel<<<(nEE + 255) / 256, 256>>>(Wq,    wt_q,  E_DIM, E_DIM);
    transpose_kernel<<<(nEE + 255) / 256, 256>>>(Wk,    wt_k,  E_DIM, E_DIM);
    transpose_kernel<<<(nEE + 255) / 256, 256>>>(Wv,    wt_v,  E_DIM, E_DIM);
    transpose_kernel<<<(nEE + 255) / 256, 256>>>(Wo,    wt_o,  E_DIM, E_DIM);
    transpose_kernel<<<(nEF + 255) / 256, 256>>>(W_ff1, wt_f1, E_DIM, FF_DIM);
    transpose_kernel<<<(nEF + 255) / 256, 256>>>(W_ff2, wt_f2, FF_DIM, E_DIM);

    dim3 blk(256);
    dim3 g256(E_DIM / 128,  M_ROWS / 128);   // (2, 1024)
    dim3 g1024(FF_DIM / 128, M_ROWS / 128);  // (8, 1024)

    // 1. t = LN(x @ W_in)
    gemm_tc<<<g256, blk>>>(x, wt_in, nullptr, t, M_ROWS, E_DIM, E_DIM, 0);
    ln_kernel<<<BN_TOK, 256>>>(t, nullptr, gin, bin, t);

    // 2. q, k, v projections
    gemm_tc<<<g256, blk>>>(t, wt_q, bq, qb, M_ROWS, E_DIM, E_DIM, 0);
    gemm_tc<<<g256, blk>>>(t, wt_k, bk, kb, M_ROWS, E_DIM, E_DIM, 0);
    gemm_tc<<<g256, blk>>>(t, wt_v, bv, vb, M_ROWS, E_DIM, E_DIM, 0);

    // 3. attention (+positional bias)
    attn_kernel<<<BN_TOK, 256>>>(qb, kb, vb, pos1, pos2, W_pos, W_bias, attn);

    // 4. o = attn @ Wo + bo   (into qb)
    gemm_tc<<<g256, blk>>>(attn, wt_o, bo, qb, M_ROWS, E_DIM, E_DIM, 0);

    // 5. h1 = LN(t + o)  -> kb
    ln_kernel<<<BN_TOK, 256>>>(qb, t, g1, b1, kb);

    // 6. ff = silu(h1 @ W_ff1)
    gemm_tc<<<g1024, blk>>>(kb, wt_f1, nullptr, ff, M_ROWS, E_DIM, FF_DIM, 1);

    // 7. o2 = ff @ W_ff2  (into vb)
    gemm_tc<<<g256, blk>>>(ff, wt_f2, nullptr, vb, M_ROWS, FF_DIM, E_DIM, 0);

    // 8. out = LN(h1 + o2)
    ln_kernel<<<BN_TOK, 256>>>(vb, kb, g2, b2, (float*)d_out);
}

// round 6
// speedup vs baseline: 3.9317x; 1.4511x over previous
#include <cuda_runtime.h>
#include <cuda_fp16.h>
#include <cstdint>
#include <cstddef>

// Problem constants
#define E_DIM   256
#define FF_DIM  1024
#define H_HEADS 8
#define D_HEAD  32
#define NH      8
#define B_SZ    2
#define N_SEQ   8192
#define M_ROWS  (B_SZ * N_SEQ * NH)      // 131072
#define BN_TOK  (B_SZ * N_SEQ)           // 16384

// Scratch (device globals: allocation-free rule)
__device__ __half g_hx [(size_t)M_ROWS * E_DIM];
__device__ __half g_ht [(size_t)M_ROWS * E_DIM];
__device__ __half g_hq [(size_t)M_ROWS * E_DIM];
__device__ __half g_hk [(size_t)M_ROWS * E_DIM];
__device__ __half g_hv [(size_t)M_ROWS * E_DIM];
__device__ __half g_ha [(size_t)M_ROWS * E_DIM];
__device__ __half g_hh1[(size_t)M_ROWS * E_DIM];
__device__ __half g_hff[(size_t)M_ROWS * FF_DIM];
__device__ float  g_fa [(size_t)M_ROWS * E_DIM];   // rotating fp32 buffer
__device__ float  g_ft [(size_t)M_ROWS * E_DIM];   // t (fp32)
__device__ float  g_fh1[(size_t)M_ROWS * E_DIM];   // h1 (fp32)

// Transposed fp16 weights [N][K]
__device__ __half g_wt_in[E_DIM * E_DIM];
__device__ __half g_wt_q [E_DIM * E_DIM];
__device__ __half g_wt_k [E_DIM * E_DIM];
__device__ __half g_wt_v [E_DIM * E_DIM];
__device__ __half g_wt_o [E_DIM * E_DIM];
__device__ __half g_wt_f1[E_DIM * FF_DIM];
__device__ __half g_wt_f2[FF_DIM * E_DIM];

__device__ __forceinline__ uint32_t smem_u32(const void* p) {
    return (uint32_t)__cvta_generic_to_shared(p);
}

// ---------------------------------------------------------------------------
// Weight transpose + fp16 round: Wt[n][k] = h(W[k][n])
// ---------------------------------------------------------------------------
__global__ __launch_bounds__(256)
void transpose_kernel(const float* __restrict__ W, __half* __restrict__ Wt, int K, int N)
{
    int idx = blockIdx.x * 256 + threadIdx.x;
    if (idx >= K * N) return;
    int k = idx / N, n = idx - k * N;
    Wt[(size_t)n * K + k] = __float2half_rn(W[idx]);
}

// fp32 -> fp16 elementwise (8 per thread)
__global__ __launch_bounds__(256)
void conv_kernel(const float* __restrict__ in, __half* __restrict__ out, size_t n8)
{
    size_t i = (size_t)blockIdx.x * 256 + threadIdx.x;
    if (i >= n8) return;
    float4 a = ((const float4*)in)[i * 2 + 0];
    float4 b = ((const float4*)in)[i * 2 + 1];
    __half2 h0 = __floats2half2_rn(a.x, a.y);
    __half2 h1 = __floats2half2_rn(a.z, a.w);
    __half2 h2 = __floats2half2_rn(b.x, b.y);
    __half2 h3 = __floats2half2_rn(b.z, b.w);
    uint4 o = { *(uint32_t*)&h0, *(uint32_t*)&h1, *(uint32_t*)&h2, *(uint32_t*)&h3 };
    ((uint4*)out)[i] = o;
}

// ---------------------------------------------------------------------------
// FP16 tensor-core GEMM: C[M,N] = A[M,K] @ Wt[N,K]^T (+bias) (+silu)
// CTA tile 128x128x64, 8 warps, warp tile 64x32, mma.m16n8k16.f16, fp32 acc.
// Outputs: Ch (fp16, optional) and/or Cf (fp32, optional).
// ---------------------------------------------------------------------------
#define BKH 64

__global__ __launch_bounds__(256)
void gemm_h(const __half* __restrict__ A, const __half* __restrict__ Wt,
            const float* __restrict__ bias,
            __half* __restrict__ Ch, float* __restrict__ Cf,
            int K, int N, int act)
{
    __shared__ __half As[128][72];   // pitch 144B
    __shared__ __half Bs[128][72];

    const int tid  = threadIdx.x;
    const int lane = tid & 31;
    const int warp = tid >> 5;
    const int wm   = (warp & 1) * 64;
    const int wn   = (warp >> 1) * 32;
    const int g    = lane >> 2;
    const int tig  = lane & 3;
    const int r8   = lane & 7;
    const int quad = lane >> 3;          // 0..3

    const size_t bm = (size_t)blockIdx.y * 128;
    const size_t bn = (size_t)blockIdx.x * 128;

    float acc[4][4][4];
#pragma unroll
    for (int mt = 0; mt < 4; mt++)
#pragma unroll
        for (int nt = 0; nt < 4; nt++)
#pragma unroll
            for (int i = 0; i < 4; i++) acc[mt][nt][i] = 0.f;

    // Register prefetch: 4 uint4 (8 halves each) per operand per thread.
    uint4 ra[4], rb[4];
#pragma unroll
    for (int i = 0; i < 4; i++) {
        int idx = i * 256 + tid;
        int row = idx >> 3;
        int cv  = (idx & 7) * 8;
        ra[i] = *(const uint4*)&A [(bm + row) * K + cv];
        rb[i] = *(const uint4*)&Wt[(bn + row) * K + cv];
    }

    for (int k0 = 0; k0 < K; k0 += BKH) {
        __syncthreads();
#pragma unroll
        for (int i = 0; i < 4; i++) {
            int idx = i * 256 + tid;
            int row = idx >> 3;
            int cv  = (idx & 7) * 8;
            *(uint4*)&As[row][cv] = ra[i];
            *(uint4*)&Bs[row][cv] = rb[i];
        }
        __syncthreads();

        if (k0 + BKH < K) {
#pragma unroll
            for (int i = 0; i < 4; i++) {
                int idx = i * 256 + tid;
                int row = idx >> 3;
                int cv  = (idx & 7) * 8;
                ra[i] = *(const uint4*)&A [(bm + row) * K + k0 + BKH + cv];
                rb[i] = *(const uint4*)&Wt[(bn + row) * K + k0 + BKH + cv];
            }
        }

#pragma unroll
        for (int kk = 0; kk < 4; kk++) {
            const int kb = kk * 16;

            // A fragments: 16x16 per mt, ldmatrix.x4
            uint32_t af[4][4];
#pragma unroll
            for (int mt = 0; mt < 4; mt++) {
                int row = wm + mt * 16 + (quad & 1) * 8 + r8;
                int col = kb + (quad >> 1) * 8;
                uint32_t addr = smem_u32(&As[row][col]);
                asm volatile(
                    "ldmatrix.sync.aligned.m8n8.x4.shared.b16 {%0,%1,%2,%3}, [%4];"
                    : "=r"(af[mt][0]), "=r"(af[mt][1]), "=r"(af[mt][2]), "=r"(af[mt][3])
                    : "r"(addr));
            }

            // B fragments: two n-tiles (8 rows each) per ldmatrix.x4
            uint32_t bf[4][2];
#pragma unroll
            for (int p = 0; p < 2; p++) {
                int row = wn + p * 16 + (quad >> 1) * 8 + r8;
                int col = kb + (quad & 1) * 8;
                uint32_t addr = smem_u32(&Bs[row][col]);
                uint32_t t0, t1, t2, t3;
                asm volatile(
                    "ldmatrix.sync.aligned.m8n8.x4.shared.b16 {%0,%1,%2,%3}, [%4];"
                    : "=r"(t0), "=r"(t1), "=r"(t2), "=r"(t3)
                    : "r"(addr));
                bf[2 * p + 0][0] = t0; bf[2 * p + 0][1] = t1;
                bf[2 * p + 1][0] = t2; bf[2 * p + 1][1] = t3;
            }

#pragma unroll
            for (int mt = 0; mt < 4; mt++)
#pragma unroll
                for (int nt = 0; nt < 4; nt++) {
                    asm volatile(
                        "mma.sync.aligned.m16n8k16.row.col.f32.f16.f16.f32 "
                        "{%0,%1,%2,%3}, {%4,%5,%6,%7}, {%8,%9}, {%0,%1,%2,%3};"
                        : "+f"(acc[mt][nt][0]), "+f"(acc[mt][nt][1]),
                          "+f"(acc[mt][nt][2]), "+f"(acc[mt][nt][3])
                        : "r"(af[mt][0]), "r"(af[mt][1]), "r"(af[mt][2]), "r"(af[mt][3]),
                          "r"(bf[nt][0]), "r"(bf[nt][1]));
                }
        }
    }

    // Epilogue
#pragma unroll
    for (int mt = 0; mt < 4; mt++) {
#pragma unroll
        for (int nt = 0; nt < 4; nt++) {
            size_t row0 = bm + wm + mt * 16 + g;
            size_t col  = bn + wn + nt * 8 + tig * 2;
            float v0 = acc[mt][nt][0], v1 = acc[mt][nt][1];
            float v2 = acc[mt][nt][2], v3 = acc[mt][nt][3];
            if (bias) {
                float b0 = bias[col], b1 = bias[col + 1];
                v0 += b0; v1 += b1; v2 += b0; v3 += b1;
            }
            if (act == 1) {
                v0 = v0 / (1.f + expf(-v0));
                v1 = v1 / (1.f + expf(-v1));
                v2 = v2 / (1.f + expf(-v2));
                v3 = v3 / (1.f + expf(-v3));
            }
            if (Cf) {
                float2 o01 = { v0, v1 };
                float2 o23 = { v2, v3 };
                *(float2*)&Cf[row0 * N + col]       = o01;
                *(float2*)&Cf[(row0 + 8) * N + col] = o23;
            }
            if (Ch) {
                __half2 h01 = __floats2half2_rn(v0, v1);
                __half2 h23 = __floats2half2_rn(v2, v3);
                *(__half2*)&Ch[row0 * N + col]       = h01;
                *(__half2*)&Ch[(row0 + 8) * N + col] = h23;
            }
        }
    }
}

// ---------------------------------------------------------------------------
// LayerNorm: LN(a (+res)) * g + b.  Outputs fp16 (opt) and fp32 (opt).
// ---------------------------------------------------------------------------
__global__ __launch_bounds__(256)
void ln_kernel(const float* __restrict__ a, const float* __restrict__ res,
               const float* __restrict__ g, const float* __restrict__ b,
               __half* __restrict__ out_h, float* __restrict__ out_f)
{
    int row  = blockIdx.x * 8 + (threadIdx.x >> 5);
    int lane = threadIdx.x & 31;
    size_t base = (size_t)row * E_DIM;

    float vals[8];
    float s = 0.f, s2 = 0.f;
#pragma unroll
    for (int i = 0; i < 8; i++) {
        float x = a[base + lane + i * 32];
        if (res) x += res[base + lane + i * 32];
        vals[i] = x;
        s += x; s2 += x * x;
    }
#pragma unroll
    for (int o = 16; o; o >>= 1) {
        s  += __shfl_xor_sync(0xffffffffu, s,  o);
        s2 += __shfl_xor_sync(0xffffffffu, s2, o);
    }
    float m   = s  * (1.f / E_DIM);
    float var = s2 * (1.f / E_DIM) - m * m;
    float inv = rsqrtf(var + 1e-5f);
#pragma unroll
    for (int i = 0; i < 8; i++) {
        int c = lane + i * 32;
        float v = (vals[i] - m) * inv * g[c] + b[c];
        if (out_f) out_f[base + c] = v;
        if (out_h) out_h[base + c] = __float2half_rn(v);
    }
}

// ---------------------------------------------------------------------------
// Attention: per-token attention over NH=8 positions, H=8 heads, d=32.
// fp16 q/k/v in, fp32 compute, fp16 out.
// ---------------------------------------------------------------------------
__global__ __launch_bounds__(256)
void attn_kernel(const __half* __restrict__ q, const __half* __restrict__ k,
                 const __half* __restrict__ v,
                 const float* __restrict__ pos1, const float* __restrict__ pos2,
                 const float* __restrict__ W_pos, const float* __restrict__ W_bias,
                 __half* __restrict__ out)
{
    int bn  = blockIdx.x;
    int tid = threadIdx.x;
    size_t base = (size_t)bn * NH * E_DIM;

    __shared__ float sq[NH][E_DIM];
    __shared__ float sk[NH][E_DIM];
    __shared__ float sv[NH][E_DIM];
    __shared__ float sbias[NH][H_HEADS];
    __shared__ float satt[H_HEADS][NH][NH];

    // 2048 halves per tensor = 256 uint4; 1 uint4/thread/tensor
    {
        int r  = tid >> 5;
        int cv = (tid & 31) * 8;
        uint4 uq = *(const uint4*)&q[base + (size_t)r * E_DIM + cv];
        uint4 uk = *(const uint4*)&k[base + (size_t)r * E_DIM + cv];
        uint4 uv = *(const uint4*)&v[base + (size_t)r * E_DIM + cv];
        const __half2* hq = (const __half2*)&uq;
        const __half2* hk = (const __half2*)&uk;
        const __half2* hv = (const __half2*)&uv;
#pragma unroll
        for (int j = 0; j < 4; j++) {
            float2 fq = __half22float2(hq[j]);
            float2 fk = __half22float2(hk[j]);
            float2 fv = __half22float2(hv[j]);
            sq[r][cv + 2 * j]     = fq.x; sq[r][cv + 2 * j + 1] = fq.y;
            sk[r][cv + 2 * j]     = fk.x; sk[r][cv + 2 * j + 1] = fk.y;
            sv[r][cv + 2 * j]     = fv.x; sv[r][cv + 2 * j + 1] = fv.y;
        }
    }

    if (tid < NH * H_HEADS) {
        int nh = tid >> 3;
        int h  = tid & 7;
        size_t pbase = ((size_t)bn * NH + nh) * 2;
        float p0 = pos1[pbase + 0], p1 = pos1[pbase + 1];
        float p2 = pos2[pbase + 0], p3 = pos2[pbase + 1];
        float acc = 0.f;
#pragma unroll
        for (int pe = 0; pe < 32; pe++) {
            float e = p0 * W_pos[0 * 32 + pe] + p1 * W_pos[1 * 32 + pe]
                    + p2 * W_pos[2 * 32 + pe] + p3 * W_pos[3 * 32 + pe];
            e = e / (1.f + expf(-e));
            acc += e * W_bias[pe * H_HEADS + h];
        }
        sbias[nh][h] = acc;
    }
    __syncthreads();

    const float scale = 0.17677669529663687f;  // 1/sqrt(32)
#pragma unroll
    for (int it = 0; it < 2; it++) {
        int idx = tid + it * 256;
        int h  = idx >> 6;
        int qi = (idx >> 3) & 7;
        int ki = idx & 7;
        float s = 0.f;
        const float* qp = &sq[qi][h * D_HEAD];
        const float* kp = &sk[ki][h * D_HEAD];
#pragma unroll
        for (int d = 0; d < D_HEAD; d++) s += qp[d] * kp[d];
        satt[h][qi][ki] = s * scale + sbias[ki][h];
    }
    __syncthreads();

    if (tid < H_HEADS * NH) {
        int h  = tid >> 3;
        int qi = tid & 7;
        float mx = satt[h][qi][0];
#pragma unroll
        for (int ki = 1; ki < NH; ki++) mx = fmaxf(mx, satt[h][qi][ki]);
        float sum = 0.f;
        float ex[NH];
#pragma unroll
        for (int ki = 0; ki < NH; ki++) { ex[ki] = expf(satt[h][qi][ki] - mx); sum += ex[ki]; }
        float rs = 1.f / sum;
#pragma unroll
        for (int ki = 0; ki < NH; ki++) satt[h][qi][ki] = ex[ki] * rs;
    }
    __syncthreads();

#pragma unroll
    for (int it = 0; it < 8; it++) {
        int idx = tid + it * 256;
        int qi = idx >> 8;
        int c  = idx & 255;
        int h  = c >> 5;
        float o = 0.f;
#pragma unroll
        for (int ki = 0; ki < NH; ki++) o += satt[h][qi][ki] * sv[ki][c];
        out[base + (size_t)qi * E_DIM + c] = __float2half_rn(o);
    }
}

// ---------------------------------------------------------------------------
// Host launcher
// ---------------------------------------------------------------------------
extern "C" void kernel_launch(void* const* d_in, const int* in_sizes, int n_in,
                              void* d_out, int out_size)
{
    const float* x     = (const float*)d_in[0];
    const float* pos1  = (const float*)d_in[1];
    const float* pos2  = (const float*)d_in[2];
    const float* W_in  = (const float*)d_in[3];
    const float* gin   = (const float*)d_in[4];
    const float* bin   = (const float*)d_in[5];
    const float* Wq    = (const float*)d_in[6];
    const float* bq    = (const float*)d_in[7];
    const float* Wk    = (const float*)d_in[8];
    const float* bk    = (const float*)d_in[9];
    const float* Wv    = (const float*)d_in[10];
    const float* bv    = (const float*)d_in[11];
    const float* Wo    = (const float*)d_in[12];
    const float* bo    = (const float*)d_in[13];
    const float* W_pos = (const float*)d_in[14];
    const float* W_bias= (const float*)d_in[15];
    const float* W_ff1 = (const float*)d_in[16];
    const float* W_ff2 = (const float*)d_in[17];
    const float* g1    = (const float*)d_in[18];
    const float* b1    = (const float*)d_in[19];
    const float* g2    = (const float*)d_in[20];
    const float* b2    = (const float*)d_in[21];

    __half *hx, *ht, *hq, *hk, *hv, *ha, *hh1, *hff;
    float  *fa, *ft, *fh1;
    __half *wt_in, *wt_q, *wt_k, *wt_v, *wt_o, *wt_f1, *wt_f2;
    cudaGetSymbolAddress((void**)&hx,  g_hx);
    cudaGetSymbolAddress((void**)&ht,  g_ht);
    cudaGetSymbolAddress((void**)&hq,  g_hq);
    cudaGetSymbolAddress((void**)&hk,  g_hk);
    cudaGetSymbolAddress((void**)&hv,  g_hv);
    cudaGetSymbolAddress((void**)&ha,  g_ha);
    cudaGetSymbolAddress((void**)&hh1, g_hh1);
    cudaGetSymbolAddress((void**)&hff, g_hff);
    cudaGetSymbolAddress((void**)&fa,  g_fa);
    cudaGetSymbolAddress((void**)&ft,  g_ft);
    cudaGetSymbolAddress((void**)&fh1, g_fh1);
    cudaGetSymbolAddress((void**)&wt_in, g_wt_in);
    cudaGetSymbolAddress((void**)&wt_q,  g_wt_q);
    cudaGetSymbolAddress((void**)&wt_k,  g_wt_k);
    cudaGetSymbolAddress((void**)&wt_v,  g_wt_v);
    cudaGetSymbolAddress((void**)&wt_o,  g_wt_o);
    cudaGetSymbolAddress((void**)&wt_f1, g_wt_f1);
    cudaGetSymbolAddress((void**)&wt_f2, g_wt_f2);

    int nEE = E_DIM * E_DIM, nEF = E_DIM * FF_DIM;
    transpose_kernel<<<(nEE + 255) / 256, 256>>>(W_in,  wt_in, E_DIM, E_DIM);
    transpose_kernel<<<(nEE + 255) / 256, 256>>>(Wq,    wt_q,  E_DIM, E_DIM);
    transpose_kernel<<<(nEE + 255) / 256, 256>>>(Wk,    wt_k,  E_DIM, E_DIM);
    transpose_kernel<<<(nEE + 255) / 256, 256>>>(Wv,    wt_v,  E_DIM, E_DIM);
    transpose_kernel<<<(nEE + 255) / 256, 256>>>(Wo,    wt_o,  E_DIM, E_DIM);
    transpose_kernel<<<(nEF + 255) / 256, 256>>>(W_ff1, wt_f1, E_DIM, FF_DIM);
    transpose_kernel<<<(nEF + 255) / 256, 256>>>(W_ff2, wt_f2, FF_DIM, E_DIM);

    // x -> fp16
    size_t x8 = (size_t)M_ROWS * E_DIM / 8;
    conv_kernel<<<(unsigned)((x8 + 255) / 256), 256>>>(x, hx, x8);

    dim3 blk(256);
    dim3 gE (E_DIM / 128,  M_ROWS / 128);   // (2, 1024)
    dim3 gFF(FF_DIM / 128, M_ROWS / 128);   // (8, 1024)

    // 1. t_pre = x @ W_in  (fp32 out) ; t = LN(t_pre) -> fp16 + fp32
    gemm_h<<<gE, blk>>>(hx, wt_in, nullptr, nullptr, fa, E_DIM, E_DIM, 0);
    ln_kernel<<<BN_TOK, 256>>>(fa, nullptr, gin, bin, ht, ft);

    // 2. q, k, v projections (fp16 out)
    gemm_h<<<gE, blk>>>(ht, wt_q, bq, hq, nullptr, E_DIM, E_DIM, 0);
    gemm_h<<<gE, blk>>>(ht, wt_k, bk, hk, nullptr, E_DIM, E_DIM, 0);
    gemm_h<<<gE, blk>>>(ht, wt_v, bv, hv, nullptr, E_DIM, E_DIM, 0);

    // 3. attention (+positional bias) -> fp16
    attn_kernel<<<BN_TOK, 256>>>(hq, hk, hv, pos1, pos2, W_pos, W_bias, ha);

    // 4. o = attn @ Wo + bo  (fp32 out, reuse fa)
    gemm_h<<<gE, blk>>>(ha, wt_o, bo, nullptr, fa, E_DIM, E_DIM, 0);

    // 5. h1 = LN(t + o) -> fp16 + fp32
    ln_kernel<<<BN_TOK, 256>>>(fa, ft, g1, b1, hh1, fh1);

    // 6. ff = silu(h1 @ W_ff1) -> fp16
    gemm_h<<<gFF, blk>>>(hh1, wt_f1, nullptr, hff, nullptr, E_DIM, FF_DIM, 1);

    // 7. o2 = ff @ W_ff2 (fp32 out, reuse fa)
    gemm_h<<<gE, blk>>>(hff, wt_f2, nullptr, nullptr, fa, FF_DIM, E_DIM, 0);

    // 8. out = LN(h1 + o2)
    ln_kernel<<<BN_TOK, 256>>>(fa, fh1, g2, b2, nullptr, (float*)d_out);
}

// round 11
// speedup vs baseline: 4.4733x; 1.1378x over previous
#include <cuda_runtime.h>
#include <cuda_fp16.h>
#include <cstdint>
#include <cstddef>

// Problem constants
#define E_DIM   256
#define FF_DIM  1024
#define H_HEADS 8
#define D_HEAD  32
#define NH      8
#define B_SZ    2
#define N_SEQ   8192
#define M_ROWS  (B_SZ * N_SEQ * NH)      // 131072
#define BN_TOK  (B_SZ * N_SEQ)           // 16384

// Scratch (device globals: allocation-free rule)
__device__ __half g_hx  [(size_t)M_ROWS * E_DIM];
__device__ __half g_ht  [(size_t)M_ROWS * E_DIM];
__device__ __half g_hqkv[(size_t)3 * M_ROWS * E_DIM];   // q|k|v contiguous
__device__ __half g_ha  [(size_t)M_ROWS * E_DIM];
__device__ __half g_hh1 [(size_t)M_ROWS * E_DIM];
__device__ __half g_hff [(size_t)M_ROWS * FF_DIM];
__device__ float  g_fa  [(size_t)M_ROWS * E_DIM];   // rotating fp32 buffer
__device__ float  g_ft  [(size_t)M_ROWS * E_DIM];   // t (fp32)
__device__ float  g_fh1 [(size_t)M_ROWS * E_DIM];   // h1 (fp32)

// Transposed fp16 weights [N][K]
__device__ __half g_wt_in [E_DIM * E_DIM];
__device__ __half g_wt_qkv[3 * E_DIM * E_DIM];      // rows 0-255 q, 256-511 k, 512-767 v
__device__ __half g_wt_o  [E_DIM * E_DIM];
__device__ __half g_wt_f1 [E_DIM * FF_DIM];
__device__ __half g_wt_f2 [FF_DIM * E_DIM];
__device__ float  g_bqkv  [3 * E_DIM];

__device__ __forceinline__ uint32_t smem_u32(const void* p) {
    return (uint32_t)__cvta_generic_to_shared(p);
}

// ---------------------------------------------------------------------------
// Weight transpose + fp16 round: Wt[n][k] = h(W[k][n])
// ---------------------------------------------------------------------------
__global__ __launch_bounds__(256)
void transpose_kernel(const float* __restrict__ W, __half* __restrict__ Wt, int K, int N)
{
    int idx = blockIdx.x * 256 + threadIdx.x;
    if (idx >= K * N) return;
    int k = idx / N, n = idx - k * N;
    Wt[(size_t)n * K + k] = __float2half_rn(W[idx]);
}

// Concatenate 3 bias vectors of 256
__global__ __launch_bounds__(256)
void concat_bias_kernel(const float* __restrict__ a, const float* __restrict__ b,
                        const float* __restrict__ c, float* __restrict__ o)
{
    int i = blockIdx.x * 256 + threadIdx.x;
    if (i < 256)       o[i] = a[i];
    else if (i < 512)  o[i] = b[i - 256];
    else if (i < 768)  o[i] = c[i - 512];
}

// fp32 -> fp16 elementwise (8 per thread)
__global__ __launch_bounds__(256)
void conv_kernel(const float* __restrict__ in, __half* __restrict__ out, size_t n8)
{
    size_t i = (size_t)blockIdx.x * 256 + threadIdx.x;
    if (i >= n8) return;
    float4 a = ((const float4*)in)[i * 2 + 0];
    float4 b = ((const float4*)in)[i * 2 + 1];
    __half2 h0 = __floats2half2_rn(a.x, a.y);
    __half2 h1 = __floats2half2_rn(a.z, a.w);
    __half2 h2 = __floats2half2_rn(b.x, b.y);
    __half2 h3 = __floats2half2_rn(b.z, b.w);
    uint4 o = { *(uint32_t*)&h0, *(uint32_t*)&h1, *(uint32_t*)&h2, *(uint32_t*)&h3 };
    ((uint4*)out)[i] = o;
}

// ---------------------------------------------------------------------------
// FP16 tensor-core GEMM: C[M,N] = A[M,K] @ Wt[N,K]^T (+bias) (+silu)
// CTA tile 128x128x64, 8 warps, warp tile 64x32, mma.m16n8k16.f16, fp32 acc.
// cp.async 2-stage pipeline, dynamic smem (72KB).
// qkv mode: N=768, output split into 3 buffers of [M][256].
// ---------------------------------------------------------------------------
#define BKH    64
#define SPITCH 72                        // halves per smem row (144B)
#define STAGE_H (128 * SPITCH)           // halves per stage-operand

__device__ __forceinline__ void load_stage(const __half* __restrict__ A,
                                           const __half* __restrict__ Wt,
                                           size_t bm, size_t bn, int K, int k0,
                                           __half* Abuf, __half* Bbuf, int tid)
{
#pragma unroll
    for (int i = 0; i < 4; i++) {
        int idx = i * 256 + tid;
        int row = idx >> 3;
        int c   = idx & 7;
        uint32_t dst = smem_u32(&Abuf[row * SPITCH + c * 8]);
        const __half* src = A + (bm + row) * (size_t)K + k0 + c * 8;
        asm volatile("cp.async.cg.shared.global [%0], [%1], 16;" :: "r"(dst), "l"(src));
    }
#pragma unroll
    for (int i = 0; i < 4; i++) {
        int idx = i * 256 + tid;
        int row = idx >> 3;
        int c   = idx & 7;
        uint32_t dst = smem_u32(&Bbuf[row * SPITCH + c * 8]);
        const __half* src = Wt + (bn + row) * (size_t)K + k0 + c * 8;
        asm volatile("cp.async.cg.shared.global [%0], [%1], 16;" :: "r"(dst), "l"(src));
    }
}

__global__ __launch_bounds__(256)
void gemm_h(const __half* __restrict__ A, const __half* __restrict__ Wt,
            const float* __restrict__ bias,
            __half* __restrict__ Ch, float* __restrict__ Cf,
            int K, int N, int act, int qkv)
{
    extern __shared__ __half smem[];
    __half* Abuf[2] = { smem,               smem + STAGE_H };
    __half* Bbuf[2] = { smem + 2 * STAGE_H, smem + 3 * STAGE_H };

    const int tid  = threadIdx.x;
    const int lane = tid & 31;
    const int warp = tid >> 5;
    const int wm   = (warp & 1) * 64;
    const int wn   = (warp >> 1) * 32;
    const int g    = lane >> 2;
    const int tig  = lane & 3;
    const int r8   = lane & 7;
    const int quad = lane >> 3;

    const size_t bm = (size_t)blockIdx.y * 128;
    const size_t bn = (size_t)blockIdx.x * 128;
    const int KT = K / BKH;

    float acc[4][4][4];
#pragma unroll
    for (int mt = 0; mt < 4; mt++)
#pragma unroll
        for (int nt = 0; nt < 4; nt++)
#pragma unroll
            for (int i = 0; i < 4; i++) acc[mt][nt][i] = 0.f;

    load_stage(A, Wt, bm, bn, K, 0, Abuf[0], Bbuf[0], tid);
    asm volatile("cp.async.commit_group;" ::: "memory");

    for (int kt = 0; kt < KT; kt++) {
        const int c = kt & 1;
        __syncthreads();   // everyone done reading buffer c^1 (prev iter)
        if (kt + 1 < KT) {
            load_stage(A, Wt, bm, bn, K, (kt + 1) * BKH, Abuf[c ^ 1], Bbuf[c ^ 1], tid);
            asm volatile("cp.async.commit_group;" ::: "memory");
            asm volatile("cp.async.wait_group 1;" ::: "memory");
        } else {
            asm volatile("cp.async.wait_group 0;" ::: "memory");
        }
        __syncthreads();

        const __half* As = Abuf[c];
        const __half* Bs = Bbuf[c];
#pragma unroll
        for (int kk = 0; kk < 4; kk++) {
            const int kb = kk * 16;

            uint32_t af[4][4];
#pragma unroll
            for (int mt = 0; mt < 4; mt++) {
                int row = wm + mt * 16 + (quad & 1) * 8 + r8;
                int col = kb + (quad >> 1) * 8;
                uint32_t addr = smem_u32(&As[row * SPITCH + col]);
                asm volatile(
                    "ldmatrix.sync.aligned.m8n8.x4.shared.b16 {%0,%1,%2,%3}, [%4];"
                    : "=r"(af[mt][0]), "=r"(af[mt][1]), "=r"(af[mt][2]), "=r"(af[mt][3])
                    : "r"(addr));
            }

            uint32_t bf[4][2];
#pragma unroll
            for (int p = 0; p < 2; p++) {
                int row = wn + p * 16 + (quad >> 1) * 8 + r8;
                int col = kb + (quad & 1) * 8;
                uint32_t addr = smem_u32(&Bs[row * SPITCH + col]);
                uint32_t t0, t1, t2, t3;
                asm volatile(
                    "ldmatrix.sync.aligned.m8n8.x4.shared.b16 {%0,%1,%2,%3}, [%4];"
                    : "=r"(t0), "=r"(t1), "=r"(t2), "=r"(t3)
                    : "r"(addr));
                bf[2 * p + 0][0] = t0; bf[2 * p + 0][1] = t1;
                bf[2 * p + 1][0] = t2; bf[2 * p + 1][1] = t3;
            }

#pragma unroll
            for (int mt = 0; mt < 4; mt++)
#pragma unroll
                for (int nt = 0; nt < 4; nt++) {
                    asm volatile(
                        "mma.sync.aligned.m16n8k16.row.col.f32.f16.f16.f32 "
                        "{%0,%1,%2,%3}, {%4,%5,%6,%7}, {%8,%9}, {%0,%1,%2,%3};"
                        : "+f"(acc[mt][nt][0]), "+f"(acc[mt][nt][1]),
                          "+f"(acc[mt][nt][2]), "+f"(acc[mt][nt][3])
                        : "r"(af[mt][0]), "r"(af[mt][1]), "r"(af[mt][2]), "r"(af[mt][3]),
                          "r"(bf[nt][0]), "r"(bf[nt][1]));
                }
        }
    }

    // Output target (qkv mode splits N=768 into 3 buffers of stride 256)
    __half* chp = Ch;
    float*  cfp = Cf;
    int n_stride = N;
    size_t col_base = bn;
    if (qkv) {
        int sel = (int)(bn >> 8);
        chp = Ch + (size_t)sel * ((size_t)M_ROWS * E_DIM);
        n_stride = E_DIM;
        col_base = bn & 255;
    }

#pragma unroll
    for (int mt = 0; mt < 4; mt++) {
#pragma unroll
        for (int nt = 0; nt < 4; nt++) {
            size_t row0 = bm + wm + mt * 16 + g;
            int    cloc = wn + nt * 8 + tig * 2;
            size_t col  = col_base + cloc;
            float v0 = acc[mt][nt][0], v1 = acc[mt][nt][1];
            float v2 = acc[mt][nt][2], v3 = acc[mt][nt][3];
            if (bias) {
                float b0 = bias[bn + cloc], b1 = bias[bn + cloc + 1];
                v0 += b0; v1 += b1; v2 += b0; v3 += b1;
            }
            if (act == 1) {
                v0 = v0 / (1.f + expf(-v0));
                v1 = v1 / (1.f + expf(-v1));
                v2 = v2 / (1.f + expf(-v2));
                v3 = v3 / (1.f + expf(-v3));
            }
            if (cfp) {
                float2 o01 = { v0, v1 };
                float2 o23 = { v2, v3 };
                *(float2*)&cfp[row0 * n_stride + col]       = o01;
                *(float2*)&cfp[(row0 + 8) * n_stride + col] = o23;
            }
            if (chp) {
                __half2 h01 = __floats2half2_rn(v0, v1);
                __half2 h23 = __floats2half2_rn(v2, v3);
                *(__half2*)&chp[row0 * n_stride + col]       = h01;
                *(__half2*)&chp[(row0 + 8) * n_stride + col] = h23;
            }
        }
    }
}
#define GEMM_SMEM (4 * STAGE_H * 2)      // 73728 bytes

// ---------------------------------------------------------------------------
// LayerNorm: LN(a (+res)) * g + b.  Outputs fp16 (opt) and fp32 (opt).
// ---------------------------------------------------------------------------
__global__ __launch_bounds__(256)
void ln_kernel(const float* __restrict__ a, const float* __restrict__ res,
               const float* __restrict__ g, const float* __restrict__ b,
               __half* __restrict__ out_h, float* __restrict__ out_f)
{
    int row  = blockIdx.x * 8 + (threadIdx.x >> 5);
    int lane = threadIdx.x & 31;
    size_t base = (size_t)row * E_DIM;

    float vals[8];
    float s = 0.f, s2 = 0.f;
#pragma unroll
    for (int i = 0; i < 8; i++) {
        float x = a[base + lane + i * 32];
        if (res) x += res[base + lane + i * 32];
        vals[i] = x;
        s += x; s2 += x * x;
    }
#pragma unroll
    for (int o = 16; o; o >>= 1) {
        s  += __shfl_xor_sync(0xffffffffu, s,  o);
        s2 += __shfl_xor_sync(0xffffffffu, s2, o);
    }
    float m   = s  * (1.f / E_DIM);
    float var = s2 * (1.f / E_DIM) - m * m;
    float inv = rsqrtf(var + 1e-5f);
#pragma unroll
    for (int i = 0; i < 8; i++) {
        int c = lane + i * 32;
        float v = (vals[i] - m) * inv * g[c] + b[c];
        if (out_f) out_f[base + c] = v;
        if (out_h) out_h[base + c] = __float2half_rn(v);
    }
}

// ---------------------------------------------------------------------------
// Attention: per-token attention over NH=8 positions, H=8 heads, d=32.
// half2 smem, fp32 accumulation.
// ---------------------------------------------------------------------------
__global__ __launch_bounds__(256)
void attn_kernel(const __half* __restrict__ qkv,
                 const float* __restrict__ pos1, const float* __restrict__ pos2,
                 const float* __restrict__ W_pos, const float* __restrict__ W_bias,
                 __half* __restrict__ out)
{
    const size_t QKV_OFF = (size_t)M_ROWS * E_DIM;
    const __half* q = qkv;
    const __half* k = qkv + QKV_OFF;
    const __half* v = qkv + 2 * QKV_OFF;

    int bn  = blockIdx.x;
    int tid = threadIdx.x;
    size_t base = (size_t)bn * NH * E_DIM;

    __shared__ __half sq[NH][E_DIM];
    __shared__ __half sk[NH][E_DIM];
    __shared__ __half sv[NH][E_DIM];
    __shared__ float  sbias[NH][H_HEADS];
    __shared__ float  satt[H_HEADS][NH][NH];

    // 2048 halves per tensor = 256 uint4; 1 uint4/thread/tensor
    {
        int r  = tid >> 5;
        int c8 = (tid & 31) * 8;
        *(uint4*)&sq[r][c8] = *(const uint4*)&q[base + (size_t)r * E_DIM + c8];
        *(uint4*)&sk[r][c8] = *(const uint4*)&k[base + (size_t)r * E_DIM + c8];
        *(uint4*)&sv[r][c8] = *(const uint4*)&v[base + (size_t)r * E_DIM + c8];
    }

    if (tid < NH * H_HEADS) {
        int nh = tid >> 3;
        int h  = tid & 7;
        size_t pbase = ((size_t)bn * NH + nh) * 2;
        float p0 = pos1[pbase + 0], p1 = pos1[pbase + 1];
        float p2 = pos2[pbase + 0], p3 = pos2[pbase + 1];
        float acc = 0.f;
#pragma unroll
        for (int pe = 0; pe < 32; pe++) {
            float e = p0 * W_pos[0 * 32 + pe] + p1 * W_pos[1 * 32 + pe]
                    + p2 * W_pos[2 * 32 + pe] + p3 * W_pos[3 * 32 + pe];
            e = e / (1.f + expf(-e));
            acc += e * W_bias[pe * H_HEADS + h];
        }
        sbias[nh][h] = acc;
    }
    __syncthreads();

    const float scale = 0.17677669529663687f;  // 1/sqrt(32)
#pragma unroll
    for (int it = 0; it < 2; it++) {
        int idx = tid + it * 256;
        int h  = idx >> 6;
        int qi = (idx >> 3) & 7;
        int ki = idx & 7;
        const __half2* qp = (const __half2*)&sq[qi][h * D_HEAD];
        const __half2* kp = (const __half2*)&sk[ki][h * D_HEAD];
        float s = 0.f;
#pragma unroll
        for (int j = 0; j < 16; j++) {
            float2 aq = __half22float2(qp[j]);
            float2 ak = __half22float2(kp[j]);
            s += aq.x * ak.x + aq.y * ak.y;
        }
        satt[h][qi][ki] = s * scale + sbias[ki][h];
    }
    __syncthreads();

    if (tid < H_HEADS * NH) {
        int h  = tid >> 3;
        int qi = tid & 7;
        float mx = satt[h][qi][0];
#pragma unroll
        for (int ki = 1; ki < NH; ki++) mx = fmaxf(mx, satt[h][qi][ki]);
        float sum = 0.f;
        float ex[NH];
#pragma unroll
        for (int ki = 0; ki < NH; ki++) { ex[ki] = expf(satt[h][qi][ki] - mx); sum += ex[ki]; }
        float rs = 1.f / sum;
#pragma unroll
        for (int ki = 0; ki < NH; ki++) satt[h][qi][ki] = ex[ki] * rs;
    }
    __syncthreads();

    // Output: 1024 half2 values, 4 per thread
#pragma unroll
    for (int it = 0; it < 4; it++) {
        int idx = it * 256 + tid;
        int qi  = idx >> 7;
        int c2  = idx & 127;          // half2 column
        int h   = c2 >> 4;
        float2 o = { 0.f, 0.f };
        const float* att = &satt[h][qi][0];
#pragma unroll
        for (int ki = 0; ki < NH; ki++) {
            float2 vv = __half22float2(((const __half2*)&sv[ki][0])[c2]);
            o.x += att[ki] * vv.x;
            o.y += att[ki] * vv.y;
        }
        *(__half2*)&out[base + (size_t)qi * E_DIM + c2 * 2] = __floats2half2_rn(o.x, o.y);
    }
}

// ---------------------------------------------------------------------------
// Host launcher
// ---------------------------------------------------------------------------
extern "C" void kernel_launch(void* const* d_in, const int* in_sizes, int n_in,
                              void* d_out, int out_size)
{
    const float* x     = (const float*)d_in[0];
    const float* pos1  = (const float*)d_in[1];
    const float* pos2  = (const float*)d_in[2];
    const float* W_in  = (const float*)d_in[3];
    const float* gin   = (const float*)d_in[4];
    const float* bin   = (const float*)d_in[5];
    const float* Wq    = (const float*)d_in[6];
    const float* bq    = (const float*)d_in[7];
    const float* Wk    = (const float*)d_in[8];
    const float* bk    = (const float*)d_in[9];
    const float* Wv    = (const float*)d_in[10];
    const float* bv    = (const float*)d_in[11];
    const float* Wo    = (const float*)d_in[12];
    const float* bo    = (const float*)d_in[13];
    const float* W_pos = (const float*)d_in[14];
    const float* W_bias= (const float*)d_in[15];
    const float* W_ff1 = (const float*)d_in[16];
    const float* W_ff2 = (const float*)d_in[17];
    const float* g1    = (const float*)d_in[18];
    const float* b1    = (const float*)d_in[19];
    const float* g2    = (const float*)d_in[20];
    const float* b2    = (const float*)d_in[21];

    __half *hx, *ht, *hqkv, *ha, *hh1, *hff;
    float  *fa, *ft, *fh1, *bqkv;
    __half *wt_in, *wt_qkv, *wt_o, *wt_f1, *wt_f2;
    cudaGetSymbolAddress((void**)&hx,   g_hx);
    cudaGetSymbolAddress((void**)&ht,   g_ht);
    cudaGetSymbolAddress((void**)&hqkv, g_hqkv);
    cudaGetSymbolAddress((void**)&ha,   g_ha);
    cudaGetSymbolAddress((void**)&hh1,  g_hh1);
    cudaGetSymbolAddress((void**)&hff,  g_hff);
    cudaGetSymbolAddress((void**)&fa,   g_fa);
    cudaGetSymbolAddress((void**)&ft,   g_ft);
    cudaGetSymbolAddress((void**)&fh1,  g_fh1);
    cudaGetSymbolAddress((void**)&bqkv,  g_bqkv);
    cudaGetSymbolAddress((void**)&wt_in, g_wt_in);
    cudaGetSymbolAddress((void**)&wt_qkv,g_wt_qkv);
    cudaGetSymbolAddress((void**)&wt_o,  g_wt_o);
    cudaGetSymbolAddress((void**)&wt_f1, g_wt_f1);
    cudaGetSymbolAddress((void**)&wt_f2, g_wt_f2);

    cudaFuncSetAttribute(gemm_h, cudaFuncAttributeMaxDynamicSharedMemorySize, GEMM_SMEM);

    int nEE = E_DIM * E_DIM, nEF = E_DIM * FF_DIM;
    transpose_kernel<<<(nEE + 255) / 256, 256>>>(W_in,  wt_in,              E_DIM, E_DIM);
    transpose_kernel<<<(nEE + 255) / 256, 256>>>(Wq,    wt_qkv,             E_DIM, E_DIM);
    transpose_kernel<<<(nEE + 255) / 256, 256>>>(Wk,    wt_qkv + 1 * nEE,   E_DIM, E_DIM);
    transpose_kernel<<<(nEE + 255) / 256, 256>>>(Wv,    wt_qkv + 2 * nEE,   E_DIM, E_DIM);
    transpose_kernel<<<(nEE + 255) / 256, 256>>>(Wo,    wt_o,               E_DIM, E_DIM);
    transpose_kernel<<<(nEF + 255) / 256, 256>>>(W_ff1, wt_f1,              E_DIM, FF_DIM);
    transpose_kernel<<<(nEF + 255) / 256, 256>>>(W_ff2, wt_f2,              FF_DIM, E_DIM);
    concat_bias_kernel<<<3, 256>>>(bq, bk, bv, bqkv);

    size_t x8 = (size_t)M_ROWS * E_DIM / 8;
    conv_kernel<<<(unsigned)((x8 + 255) / 256), 256>>>(x, hx, x8);

    dim3 blk(256);
    dim3 gE  (E_DIM / 128,     M_ROWS / 128);   // (2, 1024)
    dim3 gQKV(3 * E_DIM / 128, M_ROWS / 128);   // (6, 1024)
    dim3 gFF (FF_DIM / 128,    M_ROWS / 128);   // (8, 1024)

    // 1. t_pre = x @ W_in (fp32) ; t = LN(t_pre) -> fp16 + fp32
    gemm_h<<<gE, blk, GEMM_SMEM>>>(hx, wt_in, nullptr, nullptr, fa, E_DIM, E_DIM, 0, 0);
    ln_kernel<<<BN_TOK, 256>>>(fa, nullptr, gin, bin, ht, ft);

    // 2. fused q|k|v projection
    gemm_h<<<gQKV, blk, GEMM_SMEM>>>(ht, wt_qkv, bqkv, hqkv, nullptr, E_DIM, 3 * E_DIM, 0, 1);

    // 3. attention (+positional bias) -> fp16
    attn_kernel<<<BN_TOK, 256>>>(hqkv, pos1, pos2, W_pos, W_bias, ha);

    // 4. o = attn @ Wo + bo (fp32)
    gemm_h<<<gE, blk, GEMM_SMEM>>>(ha, wt_o, bo, nullptr, fa, E_DIM, E_DIM, 0, 0);

    // 5. h1 = LN(t + o) -> fp16 + fp32
    ln_kernel<<<BN_TOK, 256>>>(fa, ft, g1, b1, hh1, fh1);

    // 6. ff = silu(h1 @ W_ff1) -> fp16
    gemm_h<<<gFF, blk, GEMM_SMEM>>>(hh1, wt_f1, nullptr, hff, nullptr, E_DIM, FF_DIM, 1, 0);

    // 7. o2 = ff @ W_ff2 (fp32)
    gemm_h<<<gE, blk, GEMM_SMEM>>>(hff, wt_f2, nullptr, nullptr, fa, FF_DIM, E_DIM, 0, 0);

    // 8. out = LN(h1 + o2)
    ln_kernel<<<BN_TOK, 256>>>(fa, fh1, g2, b2, nullptr, (float*)d_out);
}